// round 8
// baseline (speedup 1.0000x reference)
#include <cuda_runtime.h>
#include <cuda_fp16.h>

#define NX 20000
#define NL 48
#define NK 1024
#define NT 600
#define NSTRIPE 16
#define NQ 24                 // (table, ell-group-of-8): 4 tables x 6 groups
#define TPB (NQ * NSTRIPE)    // 384 threads
#define GMAX 640              // max distinct rows for the coefficient-sweep path

// Combined fp16 table: Ch[x][tbl*48 + ell], 192 halves (384B) per x-row.
__device__ __half g_Ch[NX * 192];

// Bit-cast helpers (no SASS cost).
static __device__ __forceinline__ int h2_as_int(__half2 h) {
    return *reinterpret_cast<int*>(&h);
}
static __device__ __forceinline__ __half2 int_as_h2(int i) {
    return *reinterpret_cast<__half2*>(&i);
}

// ---------------------------------------------------------------------------
// Kernel 0: pack four [NX, NL] fp32 tables into one [NX, 192] fp16 table,
// AND zero the (poisoned / previously-accumulated) output.
// One thread per (x, table, ell-group-of-8): 2x LDG.128 + 1x STG.128.
// ---------------------------------------------------------------------------
__global__ __launch_bounds__(256) void kpack(
    const float* __restrict__ p0, const float* __restrict__ p1,
    const float* __restrict__ p2, const float* __restrict__ pe,
    float* __restrict__ out)
{
    if (blockIdx.x == 0 && threadIdx.x < 3 * NL)
        out[threadIdx.x] = 0.0f;

    int i = blockIdx.x * 256 + threadIdx.x;       // over NX*24
    int x   = i / 24;
    int sub = i % 24;
    int tbl = sub / 6;
    int eg  = sub % 6;

    const float* src = (tbl == 0 ? p0 : tbl == 1 ? p1 : tbl == 2 ? p2 : pe)
                       + x * NL + eg * 8;
    float4 va = *(const float4*)(src);
    float4 vb = *(const float4*)(src + 4);

    int4 pk;
    pk.x = h2_as_int(__floats2half2_rn(va.x, va.y));
    pk.y = h2_as_int(__floats2half2_rn(va.z, va.w));
    pk.z = h2_as_int(__floats2half2_rn(vb.x, vb.y));
    pk.w = h2_as_int(__floats2half2_rn(vb.z, vb.w));
    *(int4*)(g_Ch + x * 192 + tbl * 48 + eg * 8) = pk;
}

// ---------------------------------------------------------------------------
// Kernel 1: line-of-sight tau-integration + Cl accumulation. One block per k.
// Path A (small k, row span D <= GMAX): scatter lerp coefficients per distinct
//   row into smem, then sweep each row ONCE (1 LDG.128 per row per q-lane).
// Path B (large k): direct per-tau gather (2 LDG.128 per point per q-lane).
// ---------------------------------------------------------------------------
__global__ __launch_bounds__(TPB) void klos(
    const float* __restrict__ k,  const float* __restrict__ tau,
    const float* __restrict__ tau0p, const float* __restrict__ bx,
    const float* __restrict__ S0, const float* __restrict__ S1,
    const float* __restrict__ S2, const float* __restrict__ SE,
    const float* __restrict__ Asp, const float* __restrict__ nsp,
    float* __restrict__ out)
{
    __shared__ float sSw[4 * NT];    // S_tbl[t] * trapezoid weight
    __shared__ int2  siw[NT];        // {i0, bits(frac w)}
    __shared__ float sgam[4 * GMAX]; // path-A per-row coefficients
    __shared__ float red[TPB * 8];
    __shared__ float sscale;

    const int ik  = blockIdx.x;
    const int tid = threadIdx.x;

    const float kk   = k[ik];
    const float t0   = tau0p[0];
    const float xmin = bx[0];
    const float inv  = (float)(NX - 1) / (bx[NX - 1] - xmin);

    for (int t = tid; t < NT; t += TPB) {
        float tc = tau[t];
        float tp = (t + 1 < NT) ? tau[t + 1] : tc;
        float tm = (t > 0)      ? tau[t - 1] : tc;
        float wt = 0.5f * (tp - tm);
        sSw[0 * NT + t] = S0[ik * NT + t] * wt;
        sSw[1 * NT + t] = S1[ik * NT + t] * wt;
        sSw[2 * NT + t] = S2[ik * NT + t] * wt;
        sSw[3 * NT + t] = SE[ik * NT + t] * wt;
        float pos = (kk * (t0 - tc) - xmin) * inv;
        pos = fminf(fmaxf(pos, 0.0f), (float)(NX - 1));
        int i0 = (int)pos;
        if (i0 > NX - 2) i0 = NX - 2;
        siw[t] = make_int2(i0, __float_as_int(pos - (float)i0));
    }
    if (tid == 0) {
        // sqrt( (2/pi) * dk * k^2 * P_R(k) ), folded into T,E
        float kp = (ik + 1 < NK) ? k[ik + 1] : kk;
        float km = (ik > 0)      ? k[ik - 1] : kk;
        float dk = 0.5f * (kp - km);
        const float PI = 3.14159265358979323846f;
        float A_s = Asp[0], n_s = nsp[0];
        float pr = A_s * powf(kk * 20.0f, n_s - 1.0f)
                       * (2.0f * PI * PI / (kk * kk * kk));
        sscale = sqrtf((2.0f / PI) * dk * kk * kk * pr);
    }
    __syncthreads();

    // x = k*(tau0 - tau) decreases with t -> i0 monotone non-increasing.
    const int r0 = siw[NT - 1].x;          // min row
    const int D  = siw[0].x + 2 - r0;      // rows r0 .. siw[0].x+1 inclusive

    const int q   = tid % NQ;
    const int st  = tid / NQ;
    const int tbl = q / 6;
    const int qo  = q * 8;     // half-element offset (16B aligned)

    float a0=0.f,a1=0.f,a2=0.f,a3=0.f,a4=0.f,a5=0.f,a6=0.f,a7=0.f;

    if (D <= GMAX) {
        // ---- Path A: coefficient scatter + single row sweep ----
        for (int i = tid; i < 4 * GMAX; i += TPB) sgam[i] = 0.0f;
        __syncthreads();
        for (int t = tid; t < NT; t += TPB) {
            int2  iw = siw[t];
            float w  = __int_as_float(iw.y);
            float wm = 1.0f - w;
            int   r  = iw.x - r0;
            #pragma unroll
            for (int tb = 0; tb < 4; tb++) {
                float c = sSw[tb * NT + t];
                atomicAdd(&sgam[tb * GMAX + r],     c * wm);
                atomicAdd(&sgam[tb * GMAX + r + 1], c * w);
            }
        }
        __syncthreads();

        const float* __restrict__ grow = sgam + tbl * GMAX;
        #pragma unroll 2
        for (int r = st; r < D; r += NSTRIPE) {
            float g = grow[r];
            int4 Ar = *(const int4*)(g_Ch + (r0 + r) * 192 + qo);
            float2 f0 = __half22float2(int_as_h2(Ar.x));
            float2 f1 = __half22float2(int_as_h2(Ar.y));
            float2 f2 = __half22float2(int_as_h2(Ar.z));
            float2 f3 = __half22float2(int_as_h2(Ar.w));
            a0 = fmaf(g, f0.x, a0); a1 = fmaf(g, f0.y, a1);
            a2 = fmaf(g, f1.x, a2); a3 = fmaf(g, f1.y, a3);
            a4 = fmaf(g, f2.x, a4); a5 = fmaf(g, f2.y, a5);
            a6 = fmaf(g, f3.x, a6); a7 = fmaf(g, f3.y, a7);
        }
    } else {
        // ---- Path B: direct per-tau gather ----
        const float* __restrict__ srow = sSw + tbl * NT;
        #pragma unroll 2
        for (int t = st; t < NT; t += NSTRIPE) {
            int2  iw = siw[t];
            float w  = __int_as_float(iw.y);
            __half2 wh = __float2half2_rn(w);

            const int4* pa = (const int4*)(g_Ch + iw.x * 192 + qo);
            int4 Ar = pa[0];
            int4 Br = pa[24];      // next x-row: +192 halves = +384B

            __half2 A0 = int_as_h2(Ar.x), A1 = int_as_h2(Ar.y),
                    A2 = int_as_h2(Ar.z), A3 = int_as_h2(Ar.w);
            __half2 B0 = int_as_h2(Br.x), B1 = int_as_h2(Br.y),
                    B2 = int_as_h2(Br.z), B3 = int_as_h2(Br.w);

            __half2 r0h = __hfma2(__hsub2(B0, A0), wh, A0);
            __half2 r1h = __hfma2(__hsub2(B1, A1), wh, A1);
            __half2 r2h = __hfma2(__hsub2(B2, A2), wh, A2);
            __half2 r3h = __hfma2(__hsub2(B3, A3), wh, A3);

            float2 f0 = __half22float2(r0h);
            float2 f1 = __half22float2(r1h);
            float2 f2 = __half22float2(r2h);
            float2 f3 = __half22float2(r3h);

            float c = srow[t];
            a0 = fmaf(c, f0.x, a0); a1 = fmaf(c, f0.y, a1);
            a2 = fmaf(c, f1.x, a2); a3 = fmaf(c, f1.y, a3);
            a4 = fmaf(c, f2.x, a4); a5 = fmaf(c, f2.y, a5);
            a6 = fmaf(c, f3.x, a6); a7 = fmaf(c, f3.y, a7);
        }
    }

    float* r = red + tid * 8;
    r[0]=a0; r[1]=a1; r[2]=a2; r[3]=a3; r[4]=a4; r[5]=a5; r[6]=a6; r[7]=a7;
    __syncthreads();

    // 48 threads: thread ell sums its T (tables 0..2) and E (table 3) over
    // all stripes, scales, and accumulates Cl terms atomically.
    if (tid < NL) {
        int ell = tid;
        int g   = ell >> 3;
        int j   = ell & 7;
        float sT = 0.f, sE = 0.f;
        #pragma unroll
        for (int sp = 0; sp < NSTRIPE; sp++) {
            const float* base = red + (sp * NQ) * 8 + j;
            sT += base[(0 * 6 + g) * 8] + base[(1 * 6 + g) * 8] + base[(2 * 6 + g) * 8];
            sE += base[(3 * 6 + g) * 8];
        }
        float sc = sscale;
        float T = sT * sc, E = sE * sc;
        atomicAdd(&out[0 * NL + ell], T * T);
        atomicAdd(&out[1 * NL + ell], E * E);
        atomicAdd(&out[2 * NL + ell], T * E);
    }
}

// ---------------------------------------------------------------------------
extern "C" void kernel_launch(void* const* d_in, const int* in_sizes, int n_in,
                              void* d_out, int out_size)
{
    const float* k    = (const float*)d_in[0];
    const float* tau  = (const float*)d_in[1];
    const float* tau0 = (const float*)d_in[2];
    const float* S0   = (const float*)d_in[3];
    const float* S1   = (const float*)d_in[4];
    const float* S2   = (const float*)d_in[5];
    const float* SE   = (const float*)d_in[6];
    const float* bx   = (const float*)d_in[7];
    const float* p0   = (const float*)d_in[8];
    const float* p1   = (const float*)d_in[9];
    const float* p2   = (const float*)d_in[10];
    const float* pe   = (const float*)d_in[11];
    const float* A_s  = (const float*)d_in[12];
    const float* n_s  = (const float*)d_in[13];
    float* out = (float*)d_out;

    kpack<<<(NX * 24) / 256, 256>>>(p0, p1, p2, pe, out);
    klos<<<NK, TPB>>>(k, tau, tau0, bx, S0, S1, S2, SE, A_s, n_s, out);
}

// round 9
// speedup vs baseline: 2.4745x; 2.4745x over previous
#include <cuda_runtime.h>
#include <cuda_fp16.h>

#define NX 20000
#define NL 48
#define NK 1024
#define NT 600
#define NSTRIPE 16
#define NQ 24                 // (table, ell-group-of-8): 4 tables x 6 groups
#define TPB (NQ * NSTRIPE)    // 384 threads
#define CH 38                 // contiguous tau-chunk length for rolling path
#define DROLL 150             // rolling path when row-span D <= DROLL

// Combined fp16 table: Ch[x][tbl*48 + ell], 192 halves (384B) per x-row.
__device__ __half g_Ch[NX * 192];

// Bit-cast helpers (no SASS cost).
static __device__ __forceinline__ int h2_as_int(__half2 h) {
    return *reinterpret_cast<int*>(&h);
}
static __device__ __forceinline__ __half2 int_as_h2(int i) {
    return *reinterpret_cast<__half2*>(&i);
}

// ---------------------------------------------------------------------------
// Kernel 0: pack four [NX, NL] fp32 tables into one [NX, 192] fp16 table,
// AND zero the (poisoned / previously-accumulated) output.
// ---------------------------------------------------------------------------
__global__ __launch_bounds__(256) void kpack(
    const float* __restrict__ p0, const float* __restrict__ p1,
    const float* __restrict__ p2, const float* __restrict__ pe,
    float* __restrict__ out)
{
    if (blockIdx.x == 0 && threadIdx.x < 3 * NL)
        out[threadIdx.x] = 0.0f;

    int i = blockIdx.x * 256 + threadIdx.x;       // over NX*24
    int x   = i / 24;
    int sub = i % 24;
    int tbl = sub / 6;
    int eg  = sub % 6;

    const float* src = (tbl == 0 ? p0 : tbl == 1 ? p1 : tbl == 2 ? p2 : pe)
                       + x * NL + eg * 8;
    float4 va = *(const float4*)(src);
    float4 vb = *(const float4*)(src + 4);

    int4 pk;
    pk.x = h2_as_int(__floats2half2_rn(va.x, va.y));
    pk.y = h2_as_int(__floats2half2_rn(va.z, va.w));
    pk.z = h2_as_int(__floats2half2_rn(vb.x, vb.y));
    pk.w = h2_as_int(__floats2half2_rn(vb.z, vb.w));
    *(int4*)(g_Ch + x * 192 + tbl * 48 + eg * 8) = pk;
}

// ---------------------------------------------------------------------------
// Kernel 1: line-of-sight tau-integration + Cl accumulation. One block per k.
// Path A (D <= DROLL): contiguous tau-chunks, rolling row registers — loads
//   only on row change (~2+D/16 loads/thread instead of 75). No atomics.
// Path B: round-7 strided gather (2 LDG.128 per point, MLP-4 unroll).
// ---------------------------------------------------------------------------
__global__ __launch_bounds__(TPB) void klos(
    const float* __restrict__ k,  const float* __restrict__ tau,
    const float* __restrict__ tau0p, const float* __restrict__ bx,
    const float* __restrict__ S0, const float* __restrict__ S1,
    const float* __restrict__ S2, const float* __restrict__ SE,
    const float* __restrict__ Asp, const float* __restrict__ nsp,
    float* __restrict__ out)
{
    __shared__ float sSw[4 * NT];   // S_tbl[t] * trapezoid weight
    __shared__ int2  siw[NT];       // {i0, bits(frac w)}
    __shared__ float red[TPB * 8];
    __shared__ float sscale;

    const int ik  = blockIdx.x;
    const int tid = threadIdx.x;

    const float kk   = k[ik];
    const float t0   = tau0p[0];
    const float xmin = bx[0];
    const float inv  = (float)(NX - 1) / (bx[NX - 1] - xmin);

    for (int t = tid; t < NT; t += TPB) {
        float tc = tau[t];
        float tp = (t + 1 < NT) ? tau[t + 1] : tc;
        float tm = (t > 0)      ? tau[t - 1] : tc;
        float wt = 0.5f * (tp - tm);
        sSw[0 * NT + t] = S0[ik * NT + t] * wt;
        sSw[1 * NT + t] = S1[ik * NT + t] * wt;
        sSw[2 * NT + t] = S2[ik * NT + t] * wt;
        sSw[3 * NT + t] = SE[ik * NT + t] * wt;
        float pos = (kk * (t0 - tc) - xmin) * inv;
        pos = fminf(fmaxf(pos, 0.0f), (float)(NX - 1));
        int i0 = (int)pos;
        if (i0 > NX - 2) i0 = NX - 2;
        siw[t] = make_int2(i0, __float_as_int(pos - (float)i0));
    }
    if (tid == 0) {
        // sqrt( (2/pi) * dk * k^2 * P_R(k) ), folded into T,E
        float kp = (ik + 1 < NK) ? k[ik + 1] : kk;
        float km = (ik > 0)      ? k[ik - 1] : kk;
        float dk = 0.5f * (kp - km);
        const float PI = 3.14159265358979323846f;
        float A_s = Asp[0], n_s = nsp[0];
        float pr = A_s * powf(kk * 20.0f, n_s - 1.0f)
                       * (2.0f * PI * PI / (kk * kk * kk));
        sscale = sqrtf((2.0f / PI) * dk * kk * kk * pr);
    }
    __syncthreads();

    // x = k*(tau0 - tau) decreases with t -> i0 monotone non-increasing.
    const int D = siw[0].x - siw[NT - 1].x;   // row descent across the block

    const int q   = tid % NQ;
    const int st  = tid / NQ;
    const int tbl = q / 6;
    const float* __restrict__ srow = sSw + tbl * NT;
    const int qo  = q * 8;     // half-element offset (16B aligned)

    float a0=0.f,a1=0.f,a2=0.f,a3=0.f,a4=0.f,a5=0.f,a6=0.f,a7=0.f;

    if (D <= DROLL) {
        // ---- Path A: contiguous chunk + rolling row registers ----
        const int lo = st * CH;
        const int hi = (lo + CH < NT) ? lo + CH : NT;
        int cur = -0x40000000;
        int4 Ar = make_int4(0,0,0,0), Br = make_int4(0,0,0,0);
        for (int t = lo; t < hi; ++t) {
            int2 iw = siw[t];
            int  i0 = iw.x;
            if (i0 != cur) {
                if (i0 == cur - 1) {
                    Br = Ar;
                    Ar = *(const int4*)(g_Ch + i0 * 192 + qo);
                } else {
                    Ar = *(const int4*)(g_Ch + i0 * 192 + qo);
                    Br = *(const int4*)(g_Ch + (i0 + 1) * 192 + qo);
                }
                cur = i0;
            }
            float w = __int_as_float(iw.y);
            __half2 wh = __float2half2_rn(w);

            __half2 A0 = int_as_h2(Ar.x), A1 = int_as_h2(Ar.y),
                    A2 = int_as_h2(Ar.z), A3 = int_as_h2(Ar.w);
            __half2 B0 = int_as_h2(Br.x), B1 = int_as_h2(Br.y),
                    B2 = int_as_h2(Br.z), B3 = int_as_h2(Br.w);

            __half2 r0h = __hfma2(__hsub2(B0, A0), wh, A0);
            __half2 r1h = __hfma2(__hsub2(B1, A1), wh, A1);
            __half2 r2h = __hfma2(__hsub2(B2, A2), wh, A2);
            __half2 r3h = __hfma2(__hsub2(B3, A3), wh, A3);

            float2 f0 = __half22float2(r0h);
            float2 f1 = __half22float2(r1h);
            float2 f2 = __half22float2(r2h);
            float2 f3 = __half22float2(r3h);

            float c = srow[t];
            a0 = fmaf(c, f0.x, a0); a1 = fmaf(c, f0.y, a1);
            a2 = fmaf(c, f1.x, a2); a3 = fmaf(c, f1.y, a3);
            a4 = fmaf(c, f2.x, a4); a5 = fmaf(c, f2.y, a5);
            a6 = fmaf(c, f3.x, a6); a7 = fmaf(c, f3.y, a7);
        }
    } else {
        // ---- Path B: strided gather, MLP-4 ----
        #pragma unroll 2
        for (int t = st; t < NT; t += NSTRIPE) {
            int2  iw = siw[t];
            float w  = __int_as_float(iw.y);
            __half2 wh = __float2half2_rn(w);

            const int4* pa = (const int4*)(g_Ch + iw.x * 192 + qo);
            int4 Ar = pa[0];
            int4 Br = pa[24];      // next x-row: +192 halves = +384B

            __half2 A0 = int_as_h2(Ar.x), A1 = int_as_h2(Ar.y),
                    A2 = int_as_h2(Ar.z), A3 = int_as_h2(Ar.w);
            __half2 B0 = int_as_h2(Br.x), B1 = int_as_h2(Br.y),
                    B2 = int_as_h2(Br.z), B3 = int_as_h2(Br.w);

            __half2 r0h = __hfma2(__hsub2(B0, A0), wh, A0);
            __half2 r1h = __hfma2(__hsub2(B1, A1), wh, A1);
            __half2 r2h = __hfma2(__hsub2(B2, A2), wh, A2);
            __half2 r3h = __hfma2(__hsub2(B3, A3), wh, A3);

            float2 f0 = __half22float2(r0h);
            float2 f1 = __half22float2(r1h);
            float2 f2 = __half22float2(r2h);
            float2 f3 = __half22float2(r3h);

            float c = srow[t];
            a0 = fmaf(c, f0.x, a0); a1 = fmaf(c, f0.y, a1);
            a2 = fmaf(c, f1.x, a2); a3 = fmaf(c, f1.y, a3);
            a4 = fmaf(c, f2.x, a4); a5 = fmaf(c, f2.y, a5);
            a6 = fmaf(c, f3.x, a6); a7 = fmaf(c, f3.y, a7);
        }
    }

    float* r = red + tid * 8;
    r[0]=a0; r[1]=a1; r[2]=a2; r[3]=a3; r[4]=a4; r[5]=a5; r[6]=a6; r[7]=a7;
    __syncthreads();

    // 48 threads: thread ell sums its T (tables 0..2) and E (table 3) over
    // all stripes, scales, and accumulates Cl terms atomically (144 addrs,
    // 1024 adds each, spread over block completions -> hidden).
    if (tid < NL) {
        int ell = tid;
        int g   = ell >> 3;
        int j   = ell & 7;
        float sT = 0.f, sE = 0.f;
        #pragma unroll
        for (int sp = 0; sp < NSTRIPE; sp++) {
            const float* base = red + (sp * NQ) * 8 + j;
            sT += base[(0 * 6 + g) * 8] + base[(1 * 6 + g) * 8] + base[(2 * 6 + g) * 8];
            sE += base[(3 * 6 + g) * 8];
        }
        float sc = sscale;
        float T = sT * sc, E = sE * sc;
        atomicAdd(&out[0 * NL + ell], T * T);
        atomicAdd(&out[1 * NL + ell], E * E);
        atomicAdd(&out[2 * NL + ell], T * E);
    }
}

// ---------------------------------------------------------------------------
extern "C" void kernel_launch(void* const* d_in, const int* in_sizes, int n_in,
                              void* d_out, int out_size)
{
    const float* k    = (const float*)d_in[0];
    const float* tau  = (const float*)d_in[1];
    const float* tau0 = (const float*)d_in[2];
    const float* S0   = (const float*)d_in[3];
    const float* S1   = (const float*)d_in[4];
    const float* S2   = (const float*)d_in[5];
    const float* SE   = (const float*)d_in[6];
    const float* bx   = (const float*)d_in[7];
    const float* p0   = (const float*)d_in[8];
    const float* p1   = (const float*)d_in[9];
    const float* p2   = (const float*)d_in[10];
    const float* pe   = (const float*)d_in[11];
    const float* A_s  = (const float*)d_in[12];
    const float* n_s  = (const float*)d_in[13];
    float* out = (float*)d_out;

    kpack<<<(NX * 24) / 256, 256>>>(p0, p1, p2, pe, out);
    klos<<<NK, TPB>>>(k, tau, tau0, bx, S0, S1, S2, SE, A_s, n_s, out);
}

// round 10
// speedup vs baseline: 2.8750x; 1.1618x over previous
#include <cuda_runtime.h>
#include <cuda_fp16.h>

#define NX 20000
#define NL 48
#define NK 1024
#define NT 600
#define NSTRIPE 16
#define NQ 24                 // (table, ell-group-of-8): 4 tables x 6 groups
#define TPB (NQ * NSTRIPE)    // 384 threads
#define CH 38                 // contiguous tau-chunk length (16*38=608 >= 600)
#define DROLL 200             // deferred-coefficient path when row-span D <= DROLL

// Combined fp16 table: Ch[x][tbl*48 + ell], 192 halves (384B) per x-row.
__device__ __half g_Ch[NX * 192];

// Bit-cast helpers (no SASS cost).
static __device__ __forceinline__ int h2_as_int(__half2 h) {
    return *reinterpret_cast<int*>(&h);
}
static __device__ __forceinline__ __half2 int_as_h2(int i) {
    return *reinterpret_cast<__half2*>(&i);
}

// ---------------------------------------------------------------------------
// Kernel 0: pack four [NX, NL] fp32 tables into one [NX, 192] fp16 table,
// AND zero the (poisoned / previously-accumulated) output.
// ---------------------------------------------------------------------------
__global__ __launch_bounds__(256) void kpack(
    const float* __restrict__ p0, const float* __restrict__ p1,
    const float* __restrict__ p2, const float* __restrict__ pe,
    float* __restrict__ out)
{
    if (blockIdx.x == 0 && threadIdx.x < 3 * NL)
        out[threadIdx.x] = 0.0f;

    int i = blockIdx.x * 256 + threadIdx.x;       // over NX*24
    int x   = i / 24;
    int sub = i % 24;
    int tbl = sub / 6;
    int eg  = sub % 6;

    const float* src = (tbl == 0 ? p0 : tbl == 1 ? p1 : tbl == 2 ? p2 : pe)
                       + x * NL + eg * 8;
    float4 va = *(const float4*)(src);
    float4 vb = *(const float4*)(src + 4);

    int4 pk;
    pk.x = h2_as_int(__floats2half2_rn(va.x, va.y));
    pk.y = h2_as_int(__floats2half2_rn(va.z, va.w));
    pk.z = h2_as_int(__floats2half2_rn(vb.x, vb.y));
    pk.w = h2_as_int(__floats2half2_rn(vb.z, vb.w));
    *(int4*)(g_Ch + x * 192 + tbl * 48 + eg * 8) = pk;
}

// ---------------------------------------------------------------------------
// Kernel 1: line-of-sight tau-integration + Cl accumulation. One block per k.
// Path A (D <= DROLL): contiguous tau-chunks; per-point only accumulates the
//   two lerp coefficients (gA, gB); the 8-wide FMA + load happen only on row
//   changes (~D/16+1 events). Exact fp32 reordering, no atomics.
// Path B: strided gather (2 LDG.128 per point, unrolled for MLP).
// ---------------------------------------------------------------------------
__global__ __launch_bounds__(TPB) void klos(
    const float* __restrict__ k,  const float* __restrict__ tau,
    const float* __restrict__ tau0p, const float* __restrict__ bx,
    const float* __restrict__ S0, const float* __restrict__ S1,
    const float* __restrict__ S2, const float* __restrict__ SE,
    const float* __restrict__ Asp, const float* __restrict__ nsp,
    float* __restrict__ out)
{
    __shared__ float sSw[4 * NT];   // S_tbl[t] * trapezoid weight
    __shared__ int2  siw[NT];       // {i0, bits(frac w)}
    __shared__ float red[TPB * 8];
    __shared__ float sscale;

    const int ik  = (NK - 1) - blockIdx.x;   // heavy (large-k) blocks first
    const int tid = threadIdx.x;

    const float kk   = k[ik];
    const float t0   = tau0p[0];
    const float xmin = bx[0];
    const float inv  = (float)(NX - 1) / (bx[NX - 1] - xmin);

    for (int t = tid; t < NT; t += TPB) {
        float tc = tau[t];
        float tp = (t + 1 < NT) ? tau[t + 1] : tc;
        float tm = (t > 0)      ? tau[t - 1] : tc;
        float wt = 0.5f * (tp - tm);
        sSw[0 * NT + t] = S0[ik * NT + t] * wt;
        sSw[1 * NT + t] = S1[ik * NT + t] * wt;
        sSw[2 * NT + t] = S2[ik * NT + t] * wt;
        sSw[3 * NT + t] = SE[ik * NT + t] * wt;
        float pos = (kk * (t0 - tc) - xmin) * inv;
        pos = fminf(fmaxf(pos, 0.0f), (float)(NX - 1));
        int i0 = (int)pos;
        if (i0 > NX - 2) i0 = NX - 2;
        siw[t] = make_int2(i0, __float_as_int(pos - (float)i0));
    }
    if (tid == 0) {
        // sqrt( (2/pi) * dk * k^2 * P_R(k) ), folded into T,E
        float kp = (ik + 1 < NK) ? k[ik + 1] : kk;
        float km = (ik > 0)      ? k[ik - 1] : kk;
        float dk = 0.5f * (kp - km);
        const float PI = 3.14159265358979323846f;
        float A_s = Asp[0], n_s = nsp[0];
        float pr = A_s * powf(kk * 20.0f, n_s - 1.0f)
                       * (2.0f * PI * PI / (kk * kk * kk));
        sscale = sqrtf((2.0f / PI) * dk * kk * kk * pr);
    }
    __syncthreads();

    // x = k*(tau0 - tau) decreases with t -> i0 monotone non-increasing.
    const int D = siw[0].x - siw[NT - 1].x;   // row descent across the block

    const int q   = tid % NQ;
    const int st  = tid / NQ;
    const int tbl = q / 6;
    const float* __restrict__ srow = sSw + tbl * NT;
    const int qo  = q * 8;     // half-element offset (16B aligned)

    float a0=0.f,a1=0.f,a2=0.f,a3=0.f,a4=0.f,a5=0.f,a6=0.f,a7=0.f;

    if (D <= DROLL) {
        // ---- Path A: deferred-coefficient rolling sweep ----
        const int lo = st * CH;
        const int hi = (lo + CH < NT) ? lo + CH : NT;
        if (lo < hi) {
            int cur = siw[lo].x;
            int4 Ar = *(const int4*)(g_Ch + cur * 192 + qo);
            int4 Br = *(const int4*)(g_Ch + (cur + 1) * 192 + qo);
            float gA = 0.f, gB = 0.f;

            for (int t = lo; t < hi; ++t) {
                int2 iw = siw[t];
                if (iw.x != cur) {
                    // apply accumulated coefficients to the old row pair
                    {
                        float2 fA0 = __half22float2(int_as_h2(Ar.x));
                        float2 fA1 = __half22float2(int_as_h2(Ar.y));
                        float2 fA2 = __half22float2(int_as_h2(Ar.z));
                        float2 fA3 = __half22float2(int_as_h2(Ar.w));
                        float2 fB0 = __half22float2(int_as_h2(Br.x));
                        float2 fB1 = __half22float2(int_as_h2(Br.y));
                        float2 fB2 = __half22float2(int_as_h2(Br.z));
                        float2 fB3 = __half22float2(int_as_h2(Br.w));
                        a0 = fmaf(gA, fA0.x, fmaf(gB, fB0.x, a0));
                        a1 = fmaf(gA, fA0.y, fmaf(gB, fB0.y, a1));
                        a2 = fmaf(gA, fA1.x, fmaf(gB, fB1.x, a2));
                        a3 = fmaf(gA, fA1.y, fmaf(gB, fB1.y, a3));
                        a4 = fmaf(gA, fA2.x, fmaf(gB, fB2.x, a4));
                        a5 = fmaf(gA, fA2.y, fmaf(gB, fB2.y, a5));
                        a6 = fmaf(gA, fA3.x, fmaf(gB, fB3.x, a6));
                        a7 = fmaf(gA, fA3.y, fmaf(gB, fB3.y, a7));
                    }
                    if (iw.x == cur - 1) {
                        Br = Ar;
                        Ar = *(const int4*)(g_Ch + iw.x * 192 + qo);
                    } else {
                        Ar = *(const int4*)(g_Ch + iw.x * 192 + qo);
                        Br = *(const int4*)(g_Ch + (iw.x + 1) * 192 + qo);
                    }
                    cur = iw.x;
                    gA = 0.f; gB = 0.f;
                }
                float w  = __int_as_float(iw.y);
                float c  = srow[t];
                float cw = c * w;
                gA += c - cw;
                gB += cw;
            }
            // final apply
            {
                float2 fA0 = __half22float2(int_as_h2(Ar.x));
                float2 fA1 = __half22float2(int_as_h2(Ar.y));
                float2 fA2 = __half22float2(int_as_h2(Ar.z));
                float2 fA3 = __half22float2(int_as_h2(Ar.w));
                float2 fB0 = __half22float2(int_as_h2(Br.x));
                float2 fB1 = __half22float2(int_as_h2(Br.y));
                float2 fB2 = __half22float2(int_as_h2(Br.z));
                float2 fB3 = __half22float2(int_as_h2(Br.w));
                a0 = fmaf(gA, fA0.x, fmaf(gB, fB0.x, a0));
                a1 = fmaf(gA, fA0.y, fmaf(gB, fB0.y, a1));
                a2 = fmaf(gA, fA1.x, fmaf(gB, fB1.x, a2));
                a3 = fmaf(gA, fA1.y, fmaf(gB, fB1.y, a3));
                a4 = fmaf(gA, fA2.x, fmaf(gB, fB2.x, a4));
                a5 = fmaf(gA, fA2.y, fmaf(gB, fB2.y, a5));
                a6 = fmaf(gA, fA3.x, fmaf(gB, fB3.x, a6));
                a7 = fmaf(gA, fA3.y, fmaf(gB, fB3.y, a7));
            }
        }
    } else {
        // ---- Path B: strided gather, MLP via unroll ----
        #pragma unroll 2
        for (int t = st; t < NT; t += NSTRIPE) {
            int2  iw = siw[t];
            float w  = __int_as_float(iw.y);
            __half2 wh = __float2half2_rn(w);

            const int4* pa = (const int4*)(g_Ch + iw.x * 192 + qo);
            int4 Ar = pa[0];
            int4 Br = pa[24];      // next x-row: +192 halves = +384B

            __half2 A0 = int_as_h2(Ar.x), A1 = int_as_h2(Ar.y),
                    A2 = int_as_h2(Ar.z), A3 = int_as_h2(Ar.w);
            __half2 B0 = int_as_h2(Br.x), B1 = int_as_h2(Br.y),
                    B2 = int_as_h2(Br.z), B3 = int_as_h2(Br.w);

            __half2 r0h = __hfma2(__hsub2(B0, A0), wh, A0);
            __half2 r1h = __hfma2(__hsub2(B1, A1), wh, A1);
            __half2 r2h = __hfma2(__hsub2(B2, A2), wh, A2);
            __half2 r3h = __hfma2(__hsub2(B3, A3), wh, A3);

            float2 f0 = __half22float2(r0h);
            float2 f1 = __half22float2(r1h);
            float2 f2 = __half22float2(r2h);
            float2 f3 = __half22float2(r3h);

            float c = srow[t];
            a0 = fmaf(c, f0.x, a0); a1 = fmaf(c, f0.y, a1);
            a2 = fmaf(c, f1.x, a2); a3 = fmaf(c, f1.y, a3);
            a4 = fmaf(c, f2.x, a4); a5 = fmaf(c, f2.y, a5);
            a6 = fmaf(c, f3.x, a6); a7 = fmaf(c, f3.y, a7);
        }
    }

    float* r = red + tid * 8;
    r[0]=a0; r[1]=a1; r[2]=a2; r[3]=a3; r[4]=a4; r[5]=a5; r[6]=a6; r[7]=a7;
    __syncthreads();

    // 48 threads: thread ell sums its T (tables 0..2) and E (table 3) over
    // all stripes, scales, and accumulates Cl terms atomically.
    if (tid < NL) {
        int ell = tid;
        int g   = ell >> 3;
        int j   = ell & 7;
        float sT = 0.f, sE = 0.f;
        #pragma unroll
        for (int sp = 0; sp < NSTRIPE; sp++) {
            const float* base = red + (sp * NQ) * 8 + j;
            sT += base[(0 * 6 + g) * 8] + base[(1 * 6 + g) * 8] + base[(2 * 6 + g) * 8];
            sE += base[(3 * 6 + g) * 8];
        }
        float sc = sscale;
        float T = sT * sc, E = sE * sc;
        atomicAdd(&out[0 * NL + ell], T * T);
        atomicAdd(&out[1 * NL + ell], E * E);
        atomicAdd(&out[2 * NL + ell], T * E);
    }
}

// ---------------------------------------------------------------------------
extern "C" void kernel_launch(void* const* d_in, const int* in_sizes, int n_in,
                              void* d_out, int out_size)
{
    const float* k    = (const float*)d_in[0];
    const float* tau  = (const float*)d_in[1];
    const float* tau0 = (const float*)d_in[2];
    const float* S0   = (const float*)d_in[3];
    const float* S1   = (const float*)d_in[4];
    const float* S2   = (const float*)d_in[5];
    const float* SE   = (const float*)d_in[6];
    const float* bx   = (const float*)d_in[7];
    const float* p0   = (const float*)d_in[8];
    const float* p1   = (const float*)d_in[9];
    const float* p2   = (const float*)d_in[10];
    const float* pe   = (const float*)d_in[11];
    const float* A_s  = (const float*)d_in[12];
    const float* n_s  = (const float*)d_in[13];
    float* out = (float*)d_out;

    kpack<<<(NX * 24) / 256, 256>>>(p0, p1, p2, pe, out);
    klos<<<NK, TPB>>>(k, tau, tau0, bx, S0, S1, S2, SE, A_s, n_s, out);
}

// round 12
// speedup vs baseline: 3.0129x; 1.0480x over previous
#include <cuda_runtime.h>
#include <cuda_fp16.h>

#define NX 20000
#define NL 48
#define NK 1024
#define NT 600
#define NSTRIPE 16
#define NQ 24                 // (table, ell-group-of-8): 4 tables x 6 groups
#define TPB (NQ * NSTRIPE)    // 384 threads
#define CH 38                 // contiguous tau-chunk length (16*38=608 >= 600)
#define DROLL 360             // deferred-coefficient path when row-span D <= DROLL

// Combined fp16 table: Ch[x][tbl*48 + ell], 192 halves (384B) per x-row.
__device__ __half g_Ch[NX * 192];

// Bit-cast helpers (no SASS cost).
static __device__ __forceinline__ int h2_as_int(__half2 h) {
    return *reinterpret_cast<int*>(&h);
}
static __device__ __forceinline__ __half2 int_as_h2(int i) {
    return *reinterpret_cast<__half2*>(&i);
}

// ---------------------------------------------------------------------------
// Kernel 0: pack four [NX, NL] fp32 tables into one [NX, 192] fp16 table,
// AND zero the (poisoned / previously-accumulated) output.
// ---------------------------------------------------------------------------
__global__ __launch_bounds__(256) void kpack(
    const float* __restrict__ p0, const float* __restrict__ p1,
    const float* __restrict__ p2, const float* __restrict__ pe,
    float* __restrict__ out)
{
    if (blockIdx.x == 0 && threadIdx.x < 3 * NL)
        out[threadIdx.x] = 0.0f;

    int i = blockIdx.x * 256 + threadIdx.x;       // over NX*24
    int x   = i / 24;
    int sub = i % 24;
    int tbl = sub / 6;
    int eg  = sub % 6;

    const float* src = (tbl == 0 ? p0 : tbl == 1 ? p1 : tbl == 2 ? p2 : pe)
                       + x * NL + eg * 8;
    float4 va = *(const float4*)(src);
    float4 vb = *(const float4*)(src + 4);

    int4 pk;
    pk.x = h2_as_int(__floats2half2_rn(va.x, va.y));
    pk.y = h2_as_int(__floats2half2_rn(va.z, va.w));
    pk.z = h2_as_int(__floats2half2_rn(vb.x, vb.y));
    pk.w = h2_as_int(__floats2half2_rn(vb.z, vb.w));
    *(int4*)(g_Ch + x * 192 + tbl * 48 + eg * 8) = pk;
}

// ---------------------------------------------------------------------------
// Kernel 1: line-of-sight tau-integration + Cl accumulation. One block per k.
// Staging precomputes per (table, tau): {c(1-w), c*w} so path A's inner loop
// is two FADDs, and per tau: {row byte-offset, w bits}.
// Path A (D <= DROLL): contiguous tau-chunks, deferred-coefficient rolling.
// Path B: strided gather, unroll-4 for MLP.
// ---------------------------------------------------------------------------
__global__ __launch_bounds__(TPB) void klos(
    const float* __restrict__ k,  const float* __restrict__ tau,
    const float* __restrict__ tau0p, const float* __restrict__ bx,
    const float* __restrict__ S0, const float* __restrict__ S1,
    const float* __restrict__ S2, const float* __restrict__ SE,
    const float* __restrict__ Asp, const float* __restrict__ nsp,
    float* __restrict__ out)
{
    __shared__ float2 sCAB[4 * NT];  // {c(1-w), c*w} per (table, tau)
    __shared__ int2   siw[NT];       // {i0*384 (byte offset), bits(frac w)}
    __shared__ float  red[TPB * 8];
    __shared__ float  sscale;

    const int ik  = (NK - 1) - blockIdx.x;   // heavy (large-k) blocks first
    const int tid = threadIdx.x;

    const float kk   = k[ik];
    const float t0   = tau0p[0];
    const float xmin = bx[0];
    const float inv  = (float)(NX - 1) / (bx[NX - 1] - xmin);

    for (int t = tid; t < NT; t += TPB) {
        float tc = tau[t];
        float tp = (t + 1 < NT) ? tau[t + 1] : tc;
        float tm = (t > 0)      ? tau[t - 1] : tc;
        float wt = 0.5f * (tp - tm);
        float pos = (kk * (t0 - tc) - xmin) * inv;
        pos = fminf(fmaxf(pos, 0.0f), (float)(NX - 1));
        int i0 = (int)pos;
        if (i0 > NX - 2) i0 = NX - 2;
        float w  = pos - (float)i0;
        float wm = 1.0f - w;
        siw[t] = make_int2(i0 * 384, __float_as_int(w));
        float c0 = S0[ik * NT + t] * wt;
        float c1 = S1[ik * NT + t] * wt;
        float c2 = S2[ik * NT + t] * wt;
        float c3 = SE[ik * NT + t] * wt;
        sCAB[0 * NT + t] = make_float2(c0 * wm, c0 * w);
        sCAB[1 * NT + t] = make_float2(c1 * wm, c1 * w);
        sCAB[2 * NT + t] = make_float2(c2 * wm, c2 * w);
        sCAB[3 * NT + t] = make_float2(c3 * wm, c3 * w);
    }
    if (tid == 0) {
        // sqrt( (2/pi) * dk * k^2 * P_R(k) ), folded into T,E
        float kp = (ik + 1 < NK) ? k[ik + 1] : kk;
        float km = (ik > 0)      ? k[ik - 1] : kk;
        float dk = 0.5f * (kp - km);
        const float PI = 3.14159265358979323846f;
        float A_s = Asp[0], n_s = nsp[0];
        float pr = A_s * powf(kk * 20.0f, n_s - 1.0f)
                       * (2.0f * PI * PI / (kk * kk * kk));
        sscale = sqrtf((2.0f / PI) * dk * kk * kk * pr);
    }
    __syncthreads();

    // x decreases with t -> row offset monotone non-increasing.
    const int Db = siw[0].x - siw[NT - 1].x;   // byte descent across block

    const int q   = tid % NQ;
    const int st  = tid / NQ;
    const int tbl = q / 6;
    const float2* __restrict__ scab = sCAB + tbl * NT;
    const char* __restrict__ chbase = (const char*)g_Ch + q * 16;

    float a0=0.f,a1=0.f,a2=0.f,a3=0.f,a4=0.f,a5=0.f,a6=0.f,a7=0.f;

    if (Db <= DROLL * 384) {
        // ---- Path A: deferred-coefficient rolling sweep ----
        const int lo = st * CH;
        const int hi = (lo + CH < NT) ? lo + CH : NT;
        int cur = siw[lo].x;
        int4 Ar = *(const int4*)(chbase + cur);
        int4 Br = *(const int4*)(chbase + cur + 384);
        float gA = 0.f, gB = 0.f;

        for (int t = lo; t < hi; ++t) {
            int off = siw[t].x;
            if (off != cur) {
                // apply accumulated coefficients to the old row pair
                {
                    float2 fA0 = __half22float2(int_as_h2(Ar.x));
                    float2 fA1 = __half22float2(int_as_h2(Ar.y));
                    float2 fA2 = __half22float2(int_as_h2(Ar.z));
                    float2 fA3 = __half22float2(int_as_h2(Ar.w));
                    float2 fB0 = __half22float2(int_as_h2(Br.x));
                    float2 fB1 = __half22float2(int_as_h2(Br.y));
                    float2 fB2 = __half22float2(int_as_h2(Br.z));
                    float2 fB3 = __half22float2(int_as_h2(Br.w));
                    a0 = fmaf(gA, fA0.x, fmaf(gB, fB0.x, a0));
                    a1 = fmaf(gA, fA0.y, fmaf(gB, fB0.y, a1));
                    a2 = fmaf(gA, fA1.x, fmaf(gB, fB1.x, a2));
                    a3 = fmaf(gA, fA1.y, fmaf(gB, fB1.y, a3));
                    a4 = fmaf(gA, fA2.x, fmaf(gB, fB2.x, a4));
                    a5 = fmaf(gA, fA2.y, fmaf(gB, fB2.y, a5));
                    a6 = fmaf(gA, fA3.x, fmaf(gB, fB3.x, a6));
                    a7 = fmaf(gA, fA3.y, fmaf(gB, fB3.y, a7));
                }
                if (off == cur - 384) {
                    Br = Ar;
                    Ar = *(const int4*)(chbase + off);
                } else {
                    Ar = *(const int4*)(chbase + off);
                    Br = *(const int4*)(chbase + off + 384);
                }
                cur = off;
                gA = 0.f; gB = 0.f;
            }
            float2 cab = scab[t];
            gA += cab.x;
            gB += cab.y;
        }
        // final apply
        {
            float2 fA0 = __half22float2(int_as_h2(Ar.x));
            float2 fA1 = __half22float2(int_as_h2(Ar.y));
            float2 fA2 = __half22float2(int_as_h2(Ar.z));
            float2 fA3 = __half22float2(int_as_h2(Ar.w));
            float2 fB0 = __half22float2(int_as_h2(Br.x));
            float2 fB1 = __half22float2(int_as_h2(Br.y));
            float2 fB2 = __half22float2(int_as_h2(Br.z));
            float2 fB3 = __half22float2(int_as_h2(Br.w));
            a0 = fmaf(gA, fA0.x, fmaf(gB, fB0.x, a0));
            a1 = fmaf(gA, fA0.y, fmaf(gB, fB0.y, a1));
            a2 = fmaf(gA, fA1.x, fmaf(gB, fB1.x, a2));
            a3 = fmaf(gA, fA1.y, fmaf(gB, fB1.y, a3));
            a4 = fmaf(gA, fA2.x, fmaf(gB, fB2.x, a4));
            a5 = fmaf(gA, fA2.y, fmaf(gB, fB2.y, a5));
            a6 = fmaf(gA, fA3.x, fmaf(gB, fB3.x, a6));
            a7 = fmaf(gA, fA3.y, fmaf(gB, fB3.y, a7));
        }
    } else {
        // ---- Path B: strided gather, MLP via unroll ----
        #pragma unroll 4
        for (int t = st; t < NT; t += NSTRIPE) {
            int2  iw = siw[t];
            __half2 wh = __float2half2_rn(__int_as_float(iw.y));

            const int4* pa = (const int4*)(chbase + iw.x);
            int4 Ar = pa[0];
            int4 Br = pa[24];      // next x-row: +384B

            __half2 A0 = int_as_h2(Ar.x), A1 = int_as_h2(Ar.y),
                    A2 = int_as_h2(Ar.z), A3 = int_as_h2(Ar.w);
            __half2 B0 = int_as_h2(Br.x), B1 = int_as_h2(Br.y),
                    B2 = int_as_h2(Br.z), B3 = int_as_h2(Br.w);

            __half2 r0h = __hfma2(__hsub2(B0, A0), wh, A0);
            __half2 r1h = __hfma2(__hsub2(B1, A1), wh, A1);
            __half2 r2h = __hfma2(__hsub2(B2, A2), wh, A2);
            __half2 r3h = __hfma2(__hsub2(B3, A3), wh, A3);

            float2 f0 = __half22float2(r0h);
            float2 f1 = __half22float2(r1h);
            float2 f2 = __half22float2(r2h);
            float2 f3 = __half22float2(r3h);

            float2 cab = scab[t];
            float c = cab.x + cab.y;
            a0 = fmaf(c, f0.x, a0); a1 = fmaf(c, f0.y, a1);
            a2 = fmaf(c, f1.x, a2); a3 = fmaf(c, f1.y, a3);
            a4 = fmaf(c, f2.x, a4); a5 = fmaf(c, f2.y, a5);
            a6 = fmaf(c, f3.x, a6); a7 = fmaf(c, f3.y, a7);
        }
    }

    float* r = red + tid * 8;
    r[0]=a0; r[1]=a1; r[2]=a2; r[3]=a3; r[4]=a4; r[5]=a5; r[6]=a6; r[7]=a7;
    __syncthreads();

    // 48 threads: thread ell sums its T (tables 0..2) and E (table 3) over
    // all stripes, scales, and accumulates Cl terms atomically.
    if (tid < NL) {
        int ell = tid;
        int g   = ell >> 3;
        int j   = ell & 7;
        float sT = 0.f, sE = 0.f;
        #pragma unroll
        for (int sp = 0; sp < NSTRIPE; sp++) {
            const float* base = red + (sp * NQ) * 8 + j;
            sT += base[(0 * 6 + g) * 8] + base[(1 * 6 + g) * 8] + base[(2 * 6 + g) * 8];
            sE += base[(3 * 6 + g) * 8];
        }
        float sc = sscale;
        float T = sT * sc, E = sE * sc;
        atomicAdd(&out[0 * NL + ell], T * T);
        atomicAdd(&out[1 * NL + ell], E * E);
        atomicAdd(&out[2 * NL + ell], T * E);
    }
}

// ---------------------------------------------------------------------------
extern "C" void kernel_launch(void* const* d_in, const int* in_sizes, int n_in,
                              void* d_out, int out_size)
{
    const float* k    = (const float*)d_in[0];
    const float* tau  = (const float*)d_in[1];
    const float* tau0 = (const float*)d_in[2];
    const float* S0   = (const float*)d_in[3];
    const float* S1   = (const float*)d_in[4];
    const float* S2   = (const float*)d_in[5];
    const float* SE   = (const float*)d_in[6];
    const float* bx   = (const float*)d_in[7];
    const float* p0   = (const float*)d_in[8];
    const float* p1   = (const float*)d_in[9];
    const float* p2   = (const float*)d_in[10];
    const float* pe   = (const float*)d_in[11];
    const float* A_s  = (const float*)d_in[12];
    const float* n_s  = (const float*)d_in[13];
    float* out = (float*)d_out;

    kpack<<<(NX * 24) / 256, 256>>>(p0, p1, p2, pe, out);
    klos<<<NK, TPB>>>(k, tau, tau0, bx, S0, S1, S2, SE, A_s, n_s, out);
}

// round 13
// speedup vs baseline: 3.0413x; 1.0094x over previous
#include <cuda_runtime.h>
#include <cuda_fp16.h>

#define NX 20000
#define NL 48
#define NK 1024
#define NT 600
#define NSTRIPE 16
#define NQ 24                 // (table, ell-group-of-8): 4 tables x 6 groups
#define TPB (NQ * NSTRIPE)    // 384 threads
#define CH 38                 // contiguous tau-chunk length (16*38=608 >= 600)
#define DROLL 360             // deferred-coefficient path when row-span D <= DROLL

// Combined fp16 table: Ch[x][tbl*48 + ell], 192 halves (384B) per x-row.
__device__ __half g_Ch[NX * 192];

// Bit-cast helpers (no SASS cost).
static __device__ __forceinline__ int h2_as_int(__half2 h) {
    return *reinterpret_cast<int*>(&h);
}
static __device__ __forceinline__ __half2 int_as_h2(int i) {
    return *reinterpret_cast<__half2*>(&i);
}

// ---------------------------------------------------------------------------
// Kernel 0: pack four [NX, NL] fp32 tables into one [NX, 192] fp16 table,
// AND zero the (poisoned / previously-accumulated) output.
// ---------------------------------------------------------------------------
__global__ __launch_bounds__(256) void kpack(
    const float* __restrict__ p0, const float* __restrict__ p1,
    const float* __restrict__ p2, const float* __restrict__ pe,
    float* __restrict__ out)
{
    if (blockIdx.x == 0 && threadIdx.x < 3 * NL)
        out[threadIdx.x] = 0.0f;

    int i = blockIdx.x * 256 + threadIdx.x;       // over NX*24
    int x   = i / 24;
    int sub = i % 24;
    int tbl = sub / 6;
    int eg  = sub % 6;

    const float* src = (tbl == 0 ? p0 : tbl == 1 ? p1 : tbl == 2 ? p2 : pe)
                       + x * NL + eg * 8;
    float4 va = *(const float4*)(src);
    float4 vb = *(const float4*)(src + 4);

    int4 pk;
    pk.x = h2_as_int(__floats2half2_rn(va.x, va.y));
    pk.y = h2_as_int(__floats2half2_rn(va.z, va.w));
    pk.z = h2_as_int(__floats2half2_rn(vb.x, vb.y));
    pk.w = h2_as_int(__floats2half2_rn(vb.z, vb.w));
    *(int4*)(g_Ch + x * 192 + tbl * 48 + eg * 8) = pk;
}

// ---------------------------------------------------------------------------
// Kernel 1: line-of-sight tau-integration + Cl accumulation. One block per k.
// Staging precomputes per (table, tau): {c(1-w), c*w} so path A's inner loop
// is two FADDs, and per tau: {row byte-offset, w bits}.
// Path A (D <= DROLL): contiguous tau-chunks, deferred-coefficient rolling.
// Path B: strided gather, unroll-4 for MLP.
// ---------------------------------------------------------------------------
__global__ __launch_bounds__(TPB) void klos(
    const float* __restrict__ k,  const float* __restrict__ tau,
    const float* __restrict__ tau0p, const float* __restrict__ bx,
    const float* __restrict__ S0, const float* __restrict__ S1,
    const float* __restrict__ S2, const float* __restrict__ SE,
    const float* __restrict__ Asp, const float* __restrict__ nsp,
    float* __restrict__ out)
{
    __shared__ float2 sCAB[4 * NT];  // {c(1-w), c*w} per (table, tau)
    __shared__ int2   siw[NT];       // {i0*384 (byte offset), bits(frac w)}
    __shared__ float  red[TPB * 8];
    __shared__ float  sscale;

    const int ik  = (NK - 1) - blockIdx.x;   // heavy (large-k) blocks first
    const int tid = threadIdx.x;

    const float kk   = k[ik];
    const float t0   = tau0p[0];
    const float xmin = bx[0];
    const float inv  = (float)(NX - 1) / (bx[NX - 1] - xmin);

    for (int t = tid; t < NT; t += TPB) {
        float tc = tau[t];
        float tp = (t + 1 < NT) ? tau[t + 1] : tc;
        float tm = (t > 0)      ? tau[t - 1] : tc;
        float wt = 0.5f * (tp - tm);
        float pos = (kk * (t0 - tc) - xmin) * inv;
        pos = fminf(fmaxf(pos, 0.0f), (float)(NX - 1));
        int i0 = (int)pos;
        if (i0 > NX - 2) i0 = NX - 2;
        float w  = pos - (float)i0;
        float wm = 1.0f - w;
        siw[t] = make_int2(i0 * 384, __float_as_int(w));
        float c0 = S0[ik * NT + t] * wt;
        float c1 = S1[ik * NT + t] * wt;
        float c2 = S2[ik * NT + t] * wt;
        float c3 = SE[ik * NT + t] * wt;
        sCAB[0 * NT + t] = make_float2(c0 * wm, c0 * w);
        sCAB[1 * NT + t] = make_float2(c1 * wm, c1 * w);
        sCAB[2 * NT + t] = make_float2(c2 * wm, c2 * w);
        sCAB[3 * NT + t] = make_float2(c3 * wm, c3 * w);
    }
    if (tid == 0) {
        // sqrt( (2/pi) * dk * k^2 * P_R(k) ), folded into T,E
        float kp = (ik + 1 < NK) ? k[ik + 1] : kk;
        float km = (ik > 0)      ? k[ik - 1] : kk;
        float dk = 0.5f * (kp - km);
        const float PI = 3.14159265358979323846f;
        float A_s = Asp[0], n_s = nsp[0];
        float pr = A_s * powf(kk * 20.0f, n_s - 1.0f)
                       * (2.0f * PI * PI / (kk * kk * kk));
        sscale = sqrtf((2.0f / PI) * dk * kk * kk * pr);
    }
    __syncthreads();

    // x decreases with t -> row offset monotone non-increasing.
    const int Db = siw[0].x - siw[NT - 1].x;   // byte descent across block

    const int q   = tid % NQ;
    const int st  = tid / NQ;
    const int tbl = q / 6;
    const float2* __restrict__ scab = sCAB + tbl * NT;
    const char* __restrict__ chbase = (const char*)g_Ch + q * 16;

    float a0=0.f,a1=0.f,a2=0.f,a3=0.f,a4=0.f,a5=0.f,a6=0.f,a7=0.f;

    if (Db <= DROLL * 384) {
        // ---- Path A: deferred-coefficient rolling sweep ----
        const int lo = st * CH;
        const int hi = (lo + CH < NT) ? lo + CH : NT;
        int cur = siw[lo].x;
        int4 Ar = *(const int4*)(chbase + cur);
        int4 Br = *(const int4*)(chbase + cur + 384);
        float gA = 0.f, gB = 0.f;

        for (int t = lo; t < hi; ++t) {
            int off = siw[t].x;
            if (off != cur) {
                // apply accumulated coefficients to the old row pair
                {
                    float2 fA0 = __half22float2(int_as_h2(Ar.x));
                    float2 fA1 = __half22float2(int_as_h2(Ar.y));
                    float2 fA2 = __half22float2(int_as_h2(Ar.z));
                    float2 fA3 = __half22float2(int_as_h2(Ar.w));
                    float2 fB0 = __half22float2(int_as_h2(Br.x));
                    float2 fB1 = __half22float2(int_as_h2(Br.y));
                    float2 fB2 = __half22float2(int_as_h2(Br.z));
                    float2 fB3 = __half22float2(int_as_h2(Br.w));
                    a0 = fmaf(gA, fA0.x, fmaf(gB, fB0.x, a0));
                    a1 = fmaf(gA, fA0.y, fmaf(gB, fB0.y, a1));
                    a2 = fmaf(gA, fA1.x, fmaf(gB, fB1.x, a2));
                    a3 = fmaf(gA, fA1.y, fmaf(gB, fB1.y, a3));
                    a4 = fmaf(gA, fA2.x, fmaf(gB, fB2.x, a4));
                    a5 = fmaf(gA, fA2.y, fmaf(gB, fB2.y, a5));
                    a6 = fmaf(gA, fA3.x, fmaf(gB, fB3.x, a6));
                    a7 = fmaf(gA, fA3.y, fmaf(gB, fB3.y, a7));
                }
                if (off == cur - 384) {
                    Br = Ar;
                    Ar = *(const int4*)(chbase + off);
                } else {
                    Ar = *(const int4*)(chbase + off);
                    Br = *(const int4*)(chbase + off + 384);
                }
                cur = off;
                gA = 0.f; gB = 0.f;
            }
            float2 cab = scab[t];
            gA += cab.x;
            gB += cab.y;
        }
        // final apply
        {
            float2 fA0 = __half22float2(int_as_h2(Ar.x));
            float2 fA1 = __half22float2(int_as_h2(Ar.y));
            float2 fA2 = __half22float2(int_as_h2(Ar.z));
            float2 fA3 = __half22float2(int_as_h2(Ar.w));
            float2 fB0 = __half22float2(int_as_h2(Br.x));
            float2 fB1 = __half22float2(int_as_h2(Br.y));
            float2 fB2 = __half22float2(int_as_h2(Br.z));
            float2 fB3 = __half22float2(int_as_h2(Br.w));
            a0 = fmaf(gA, fA0.x, fmaf(gB, fB0.x, a0));
            a1 = fmaf(gA, fA0.y, fmaf(gB, fB0.y, a1));
            a2 = fmaf(gA, fA1.x, fmaf(gB, fB1.x, a2));
            a3 = fmaf(gA, fA1.y, fmaf(gB, fB1.y, a3));
            a4 = fmaf(gA, fA2.x, fmaf(gB, fB2.x, a4));
            a5 = fmaf(gA, fA2.y, fmaf(gB, fB2.y, a5));
            a6 = fmaf(gA, fA3.x, fmaf(gB, fB3.x, a6));
            a7 = fmaf(gA, fA3.y, fmaf(gB, fB3.y, a7));
        }
    } else {
        // ---- Path B: strided gather, MLP via unroll ----
        #pragma unroll 4
        for (int t = st; t < NT; t += NSTRIPE) {
            int2  iw = siw[t];
            __half2 wh = __float2half2_rn(__int_as_float(iw.y));

            const int4* pa = (const int4*)(chbase + iw.x);
            int4 Ar = pa[0];
            int4 Br = pa[24];      // next x-row: +384B

            __half2 A0 = int_as_h2(Ar.x), A1 = int_as_h2(Ar.y),
                    A2 = int_as_h2(Ar.z), A3 = int_as_h2(Ar.w);
            __half2 B0 = int_as_h2(Br.x), B1 = int_as_h2(Br.y),
                    B2 = int_as_h2(Br.z), B3 = int_as_h2(Br.w);

            __half2 r0h = __hfma2(__hsub2(B0, A0), wh, A0);
            __half2 r1h = __hfma2(__hsub2(B1, A1), wh, A1);
            __half2 r2h = __hfma2(__hsub2(B2, A2), wh, A2);
            __half2 r3h = __hfma2(__hsub2(B3, A3), wh, A3);

            float2 f0 = __half22float2(r0h);
            float2 f1 = __half22float2(r1h);
            float2 f2 = __half22float2(r2h);
            float2 f3 = __half22float2(r3h);

            float2 cab = scab[t];
            float c = cab.x + cab.y;
            a0 = fmaf(c, f0.x, a0); a1 = fmaf(c, f0.y, a1);
            a2 = fmaf(c, f1.x, a2); a3 = fmaf(c, f1.y, a3);
            a4 = fmaf(c, f2.x, a4); a5 = fmaf(c, f2.y, a5);
            a6 = fmaf(c, f3.x, a6); a7 = fmaf(c, f3.y, a7);
        }
    }

    float* r = red + tid * 8;
    r[0]=a0; r[1]=a1; r[2]=a2; r[3]=a3; r[4]=a4; r[5]=a5; r[6]=a6; r[7]=a7;
    __syncthreads();

    // 48 threads: thread ell sums its T (tables 0..2) and E (table 3) over
    // all stripes, scales, and accumulates Cl terms atomically.
    if (tid < NL) {
        int ell = tid;
        int g   = ell >> 3;
        int j   = ell & 7;
        float sT = 0.f, sE = 0.f;
        #pragma unroll
        for (int sp = 0; sp < NSTRIPE; sp++) {
            const float* base = red + (sp * NQ) * 8 + j;
            sT += base[(0 * 6 + g) * 8] + base[(1 * 6 + g) * 8] + base[(2 * 6 + g) * 8];
            sE += base[(3 * 6 + g) * 8];
        }
        float sc = sscale;
        float T = sT * sc, E = sE * sc;
        atomicAdd(&out[0 * NL + ell], T * T);
        atomicAdd(&out[1 * NL + ell], E * E);
        atomicAdd(&out[2 * NL + ell], T * E);
    }
}

// ---------------------------------------------------------------------------
extern "C" void kernel_launch(void* const* d_in, const int* in_sizes, int n_in,
                              void* d_out, int out_size)
{
    const float* k    = (const float*)d_in[0];
    const float* tau  = (const float*)d_in[1];
    const float* tau0 = (const float*)d_in[2];
    const float* S0   = (const float*)d_in[3];
    const float* S1   = (const float*)d_in[4];
    const float* S2   = (const float*)d_in[5];
    const float* SE   = (const float*)d_in[6];
    const float* bx   = (const float*)d_in[7];
    const float* p0   = (const float*)d_in[8];
    const float* p1   = (const float*)d_in[9];
    const float* p2   = (const float*)d_in[10];
    const float* pe   = (const float*)d_in[11];
    const float* A_s  = (const float*)d_in[12];
    const float* n_s  = (const float*)d_in[13];
    float* out = (float*)d_out;

    kpack<<<(NX * 24) / 256, 256>>>(p0, p1, p2, pe, out);
    klos<<<NK, TPB>>>(k, tau, tau0, bx, S0, S1, S2, SE, A_s, n_s, out);
}